// round 1
// baseline (speedup 1.0000x reference)
#include <cuda_runtime.h>
#include <cstdint>

// ---------------------------------------------------------------------------
// Problem constants
// ---------------------------------------------------------------------------
#define BS 4
#define LQ 1024
#define EMBED 256
#define NH 8
#define NL 4
#define NP 16
#define HD 32
#define LEN_V 5440

// d_out layout: [output (4*1024*256)] [sampling_locations (4*1024*1024)] [attn (4*1024*512)]
#define OUT_ELEMS   (BS * LQ * EMBED)            // 1048576
#define LOC_OFFSET  (OUT_ELEMS)                  // 1048576
#define LOC_ELEMS   (BS * LQ * NH * NL * NP * 2) // 4194304
#define ATTN_OFFSET (LOC_OFFSET + LOC_ELEMS)     // 5242880
#define ATTN_ELEMS  (BS * LQ * NH * NL * NP)     // 2097152

__constant__ int   c_H[NL]     = {64, 32, 16, 8};
__constant__ int   c_W[NL]     = {64, 32, 16, 8};
__constant__ int   c_start[NL] = {0, 4096, 5120, 5376};

// Scratch (static device allocations are allowed)
__device__ float g_v[BS * LEN_V * EMBED];   // projected value, [b, lv, h, d] ~22.3 MB
__device__ float g_mid[BS * LQ * EMBED];    // pre-W_out accumulation, [b, q, h, d] 4 MB

// ---------------------------------------------------------------------------
// Generic fp32 GEMM:  C[M,N] = A[M,K] @ B[K,N] + bias[N]
// Tiles: 64x64x16, 256 threads, 4x4 register microtile per thread.
// All M,N used here are exact multiples of 64; K multiple of 16. No bounds checks.
// ---------------------------------------------------------------------------
#define BM 64
#define BN 64
#define BK 16

__global__ __launch_bounds__(256) void gemm_bias_kernel(
    const float* __restrict__ A, const float* __restrict__ B,
    const float* __restrict__ bias, float* __restrict__ C,
    int M, int N, int K)
{
    __shared__ float As[BK][BM + 1];
    __shared__ float Bs[BK][BN + 1];

    const int tid = threadIdx.x;
    const int tx = tid & 15;         // 0..15 -> n microtile
    const int ty = tid >> 4;         // 0..15 -> m microtile
    const int m0 = blockIdx.y * BM;
    const int n0 = blockIdx.x * BN;

    // A-tile load mapping: 1024 elems / 256 threads = 4 each
    const int ak = tid & 15;         // k within tile (coalesced along K)
    const int am = tid >> 4;         // base m (0..15), +16*r
    // B-tile load mapping
    const int bn = tid & 63;         // n within tile (coalesced along N)
    const int bk = tid >> 6;         // base k (0..3), +4*r

    float acc[4][4] = {};

    for (int k0 = 0; k0 < K; k0 += BK) {
#pragma unroll
        for (int r = 0; r < 4; r++) {
            int m = am + 16 * r;
            As[ak][m] = A[(size_t)(m0 + m) * K + k0 + ak];
        }
#pragma unroll
        for (int r = 0; r < 4; r++) {
            int k = bk + 4 * r;
            Bs[k][bn] = B[(size_t)(k0 + k) * N + n0 + bn];
        }
        __syncthreads();

#pragma unroll
        for (int k = 0; k < BK; k++) {
            float a[4], b[4];
#pragma unroll
            for (int i = 0; i < 4; i++) a[i] = As[k][ty * 4 + i];
#pragma unroll
            for (int j = 0; j < 4; j++) b[j] = Bs[k][tx * 4 + j];
#pragma unroll
            for (int i = 0; i < 4; i++)
#pragma unroll
                for (int j = 0; j < 4; j++)
                    acc[i][j] = fmaf(a[i], b[j], acc[i][j]);
        }
        __syncthreads();
    }

#pragma unroll
    for (int i = 0; i < 4; i++) {
        int m = m0 + ty * 4 + i;
#pragma unroll
        for (int j = 0; j < 4; j++) {
            int n = n0 + tx * 4 + j;
            C[(size_t)m * N + n] = acc[i][j] + bias[n];
        }
    }
}

// ---------------------------------------------------------------------------
// Transform kernel: one block per (b,q), 8 warps = 8 heads.
//  - in-place softmax over 64 logits per head  (attn region of d_out)
//  - in-place sampling_locations = poly(ref) + offsets/normalizer (loc region)
// ---------------------------------------------------------------------------
__global__ __launch_bounds__(256) void transform_kernel(
    const float* __restrict__ refp,   // [bs, Lq, 8]
    float* __restrict__ loc,          // [bs, Lq, nH, nL, nP, 2]  (holds raw offsets on entry)
    float* __restrict__ attn)         // [bs, Lq, nH, 64]         (holds logits on entry)
{
    const int bq = blockIdx.x;                 // 0..4095
    const int h = threadIdx.x >> 5;            // warp == head
    const int lane = threadIdx.x & 31;

    // ---- reference polynomial coefficients (broadcast loads) ----
    const float* rp = refp + (size_t)bq * 8;
    const float rx0 = rp[0], rx1 = rp[1], rx2 = rp[2], rx3 = rp[3];
    const float ry0 = rp[4], ry1 = rp[5], ry2 = rp[6], ry3 = rp[7];

    // ---- softmax over 64 per head ----
    float* ah = attn + ((size_t)bq * NH + h) * 64;
    float v0 = ah[lane];
    float v1 = ah[lane + 32];
    float mx = fmaxf(v0, v1);
#pragma unroll
    for (int o = 16; o > 0; o >>= 1)
        mx = fmaxf(mx, __shfl_xor_sync(0xFFFFFFFFu, mx, o));
    float e0 = expf(v0 - mx);
    float e1 = expf(v1 - mx);
    float s = e0 + e1;
#pragma unroll
    for (int o = 16; o > 0; o >>= 1)
        s += __shfl_xor_sync(0xFFFFFFFFu, s, o);
    float inv = 1.0f / s;
    ah[lane]      = e0 * inv;
    ah[lane + 32] = e1 * inv;

    // ---- sampling locations: 128 elements per head ----
    float* lh = loc + ((size_t)bq * NH + h) * (NL * NP * 2);
#pragma unroll
    for (int r = 0; r < 4; r++) {
        int e = r * 32 + lane;        // 0..127
        int lvl = e >> 5;
        int p = (e >> 1) & 15;
        int c = e & 1;
        float lam = (float)p * (1.0f / 15.0f);
        float pnt;
        if (c == 0) pnt = ((rx0 * lam + rx1) * lam + rx2) * lam + rx3;
        else        pnt = ((ry0 * lam + ry1) * lam + ry2) * lam + ry3;
        float norm = (c == 0) ? (float)c_W[lvl] : (float)c_H[lvl];
        lh[e] = pnt + lh[e] / norm;
    }
}

// ---------------------------------------------------------------------------
// Gather kernel: one block per (b,q), warp per head, lane = channel d (hd=32).
// acc[d] = sum over (lvl,p) of attn * bilinear(v_level, loc)
// ---------------------------------------------------------------------------
__global__ __launch_bounds__(256) void gather_kernel(
    const float* __restrict__ v,     // [bs, LEN_V, NH, HD]
    const float* __restrict__ loc,   // [bs, Lq, NH, NL, NP, 2]
    const float* __restrict__ attn,  // [bs, Lq, NH, NL, NP]
    float* __restrict__ out)         // [bs, Lq, NH, HD]
{
    const int bq = blockIdx.x;
    const int b = bq >> 10;
    const int h = threadIdx.x >> 5;
    const int d = threadIdx.x & 31;

    const float* lh = loc  + ((size_t)bq * NH + h) * (NL * NP * 2);
    const float* ah = attn + ((size_t)bq * NH + h) * (NL * NP);
    // base of v for this (b, head, channel)
    const float* vb = v + (size_t)b * LEN_V * EMBED + h * HD + d;

    float acc = 0.0f;

#pragma unroll
    for (int lvl = 0; lvl < NL; lvl++) {
        const int W = c_W[lvl];
        const int H = c_H[lvl];
        const float* vl = vb + (size_t)c_start[lvl] * EMBED;
        const float fW = (float)W, fH = (float)H;

#pragma unroll 4
        for (int p = 0; p < NP; p++) {
            int sp = lvl * NP + p;
            float lx = __ldg(&lh[sp * 2 + 0]);
            float ly = __ldg(&lh[sp * 2 + 1]);
            float a  = __ldg(&ah[sp]);

            float x = lx * fW - 0.5f;
            float y = ly * fH - 0.5f;
            float x0f = floorf(x);
            float y0f = floorf(y);
            float wx = x - x0f;
            float wy = y - y0f;
            int x0 = (int)x0f, y0 = (int)y0f;
            int x1 = x0 + 1,   y1 = y0 + 1;

            bool vx0 = (x0 >= 0) & (x0 < W);
            bool vx1 = (x1 >= 0) & (x1 < W);
            bool vy0 = (y0 >= 0) & (y0 < H);
            bool vy1 = (y1 >= 0) & (y1 < H);

            float w00 = (vx0 & vy0) ? (1.0f - wx) * (1.0f - wy) : 0.0f;
            float w10 = (vx1 & vy0) ? wx * (1.0f - wy)          : 0.0f;
            float w01 = (vx0 & vy1) ? (1.0f - wx) * wy          : 0.0f;
            float w11 = (vx1 & vy1) ? wx * wy                   : 0.0f;

            int cx0 = min(max(x0, 0), W - 1);
            int cx1 = min(max(x1, 0), W - 1);
            int cy0 = min(max(y0, 0), H - 1);
            int cy1 = min(max(y1, 0), H - 1);

            float s = 0.0f;
            // conditions are warp-uniform (same loc for all lanes): cheap skips
            if (w00 > 0.0f) s = fmaf(w00, __ldg(&vl[(size_t)(cy0 * W + cx0) * EMBED]), s);
            if (w10 > 0.0f) s = fmaf(w10, __ldg(&vl[(size_t)(cy0 * W + cx1) * EMBED]), s);
            if (w01 > 0.0f) s = fmaf(w01, __ldg(&vl[(size_t)(cy1 * W + cx0) * EMBED]), s);
            if (w11 > 0.0f) s = fmaf(w11, __ldg(&vl[(size_t)(cy1 * W + cx1) * EMBED]), s);
            acc = fmaf(a, s, acc);
        }
    }

    out[((size_t)bq * NH + h) * HD + d] = acc;
}

// ---------------------------------------------------------------------------
// Launch
// ---------------------------------------------------------------------------
extern "C" void kernel_launch(void* const* d_in, const int* in_sizes, int n_in,
                              void* d_out, int out_size)
{
    const float* query  = (const float*)d_in[0];   // [4,1024,256]
    const float* refp   = (const float*)d_in[1];   // [4,1024,8]
    const float* value  = (const float*)d_in[2];   // [4,5440,256]
    const float* W_val  = (const float*)d_in[3];   // [256,256]
    const float* b_val  = (const float*)d_in[4];   // [256]
    const float* W_off  = (const float*)d_in[5];   // [256,1024]
    const float* b_off  = (const float*)d_in[6];   // [1024]
    const float* W_attn = (const float*)d_in[7];   // [256,512]
    const float* b_attn = (const float*)d_in[8];   // [512]
    const float* W_out  = (const float*)d_in[9];   // [256,256]
    const float* b_out  = (const float*)d_in[10];  // [256]

    float* out  = (float*)d_out;                   // output region
    float* loc  = out + LOC_OFFSET;                // sampling_locations region
    float* attn = out + ATTN_OFFSET;               // attn region

    float* gv;
    float* gmid;
    cudaGetSymbolAddress((void**)&gv, g_v);
    cudaGetSymbolAddress((void**)&gmid, g_mid);

    // 1. value projection: [21760,256] = [21760,256] @ [256,256]
    {
        dim3 grid(EMBED / BN, (BS * LEN_V) / BM);
        gemm_bias_kernel<<<grid, 256>>>(value, W_val, b_val, gv, BS * LEN_V, EMBED, EMBED);
    }
    // 2. sampling offsets straight into loc region: [4096,1024]
    {
        dim3 grid(1024 / BN, (BS * LQ) / BM);
        gemm_bias_kernel<<<grid, 256>>>(query, W_off, b_off, loc, BS * LQ, 1024, EMBED);
    }
    // 3. attn logits straight into attn region: [4096,512]
    {
        dim3 grid(512 / BN, (BS * LQ) / BM);
        gemm_bias_kernel<<<grid, 256>>>(query, W_attn, b_attn, attn, BS * LQ, 512, EMBED);
    }
    // 4. in-place softmax + sampling-location transform
    transform_kernel<<<BS * LQ, 256>>>(refp, loc, attn);

    // 5. bilinear gather + attention-weighted sum
    gather_kernel<<<BS * LQ, 256>>>(gv, loc, attn, gmid);

    // 6. output projection: [4096,256] @ [256,256]
    {
        dim3 grid(EMBED / BN, (BS * LQ) / BM);
        gemm_bias_kernel<<<grid, 256>>>(gmid, W_out, b_out, out, BS * LQ, EMBED, EMBED);
    }
}